// round 2
// baseline (speedup 1.0000x reference)
#include <cuda_runtime.h>
#include <cuda_bf16.h>
#include <math.h>

// Problem constants (fixed shapes for this problem)
#define NN     20000
#define EE     400000
#define ETOT   420000      // E + N self loops
#define INC    768
#define HID    128
#define HEADS  4
#define FMAX   512         // HEADS*HID

// ---------------- device scratch (static, no allocation) ----------------
__device__ float g_feat[(size_t)NN * FMAX];   // activation output / next layer input
__device__ float g_hlin[(size_t)NN * FMAX];   // GEMM output of current layer
__device__ float g_agg [(size_t)NN * FMAX];   // edge-aggregation accumulator
__device__ float g_asrc[(size_t)NN * HEADS];
__device__ float g_adst[(size_t)NN * HEADS];
__device__ float g_m   [(size_t)NN * HEADS];
__device__ float g_s   [(size_t)NN * HEADS];
__device__ float g_e   [(size_t)ETOT * HEADS];

// ---------------- helpers ----------------
__device__ __forceinline__ int clampN(int v) {
    return v < 0 ? 0 : (v >= NN ? NN - 1 : v);
}

__device__ __forceinline__ void atomicMaxFloat(float* addr, float v) {
    if (v >= 0.f) atomicMax((int*)addr, __float_as_int(v));
    else          atomicMin((unsigned int*)addr, __float_as_uint(v));
}

__global__ void fill_kernel(float* __restrict__ p, float v, int n) {
    int i = blockIdx.x * blockDim.x + threadIdx.x;
    if (i < n) p[i] = v;
}

// ---------------- GEMM: C[M,N] = A[M,K] @ B[K,N], fp32 ----------------
// BM=64, BN=64, BK=16, 256 threads, 4x4 micro-tile per thread.
__global__ void gemm_kernel(const float* __restrict__ A,
                            const float* __restrict__ B,
                            float* __restrict__ C,
                            int M, int K, int N) {
    __shared__ float As[64][16];
    __shared__ float Bs[16][64];
    const int tx = threadIdx.x & 15;     // 0..15
    const int ty = threadIdx.x >> 4;     // 0..15
    const int row0 = blockIdx.y * 64;
    const int col0 = blockIdx.x * 64;

    float acc[4][4];
#pragma unroll
    for (int i = 0; i < 4; i++)
#pragma unroll
        for (int j = 0; j < 4; j++) acc[i][j] = 0.f;

    for (int k0 = 0; k0 < K; k0 += 16) {
        // load A tile (64x16)
#pragma unroll
        for (int t = 0; t < 4; t++) {
            int i = threadIdx.x + t * 256;
            int r = i >> 4, c = i & 15;
            int gr = row0 + r;
            As[r][c] = (gr < M) ? A[(size_t)gr * K + k0 + c] : 0.f;
        }
        // load B tile (16x64)
#pragma unroll
        for (int t = 0; t < 4; t++) {
            int i = threadIdx.x + t * 256;
            int r = i >> 6, c = i & 63;
            Bs[r][c] = B[(size_t)(k0 + r) * N + col0 + c];
        }
        __syncthreads();
#pragma unroll
        for (int k = 0; k < 16; k++) {
            float a[4], b[4];
#pragma unroll
            for (int i = 0; i < 4; i++) a[i] = As[ty * 4 + i][k];
#pragma unroll
            for (int j = 0; j < 4; j++) b[j] = Bs[k][tx * 4 + j];
#pragma unroll
            for (int i = 0; i < 4; i++)
#pragma unroll
                for (int j = 0; j < 4; j++) acc[i][j] = fmaf(a[i], b[j], acc[i][j]);
        }
        __syncthreads();
    }
#pragma unroll
    for (int i = 0; i < 4; i++) {
        int gr = row0 + ty * 4 + i;
        if (gr < M) {
#pragma unroll
            for (int j = 0; j < 4; j++)
                C[(size_t)gr * N + col0 + tx * 4 + j] = acc[i][j];
        }
    }
}

// ---------------- alpha: per (node, head) warp dot products ----------------
__global__ void alpha_kernel(const float* __restrict__ hlin,
                             const float* __restrict__ a_src,
                             const float* __restrict__ a_dst,
                             float* __restrict__ asrc,
                             float* __restrict__ adst, int H) {
    int gw = (blockIdx.x * blockDim.x + threadIdx.x) >> 5;
    int lane = threadIdx.x & 31;
    if (gw >= NN * H) return;
    int n = gw / H, h = gw - n * H;
    const float* hp = hlin + ((size_t)n * H + h) * HID;
    const float* as = a_src + h * HID;
    const float* ad = a_dst + h * HID;
    float ss = 0.f, sd = 0.f;
#pragma unroll
    for (int i = 0; i < HID / 32; i++) {
        float v = hp[lane + i * 32];
        ss = fmaf(v, as[lane + i * 32], ss);
        sd = fmaf(v, ad[lane + i * 32], sd);
    }
#pragma unroll
    for (int o = 16; o; o >>= 1) {
        ss += __shfl_xor_sync(0xffffffffu, ss, o);
        sd += __shfl_xor_sync(0xffffffffu, sd, o);
    }
    if (lane == 0) { asrc[gw] = ss; adst[gw] = sd; }
}

// ---------------- edge pass A: logits + segment max ----------------
__global__ void edgeA_kernel(const int* __restrict__ ei,
                             const float* __restrict__ asrc,
                             const float* __restrict__ adst,
                             float* __restrict__ e_out,
                             float* __restrict__ m, int H) {
    int idx = blockIdx.x * blockDim.x + threadIdx.x;
    if (idx >= ETOT * H) return;
    int e = idx / H, h = idx - e * H;
    int s, d;
    if (e < EE) { s = clampN(ei[e]); d = clampN(ei[EE + e]); } else { s = d = e - EE; }
    float v = asrc[(size_t)s * H + h] + adst[(size_t)d * H + h];
    v = (v > 0.f) ? v : 0.2f * v;   // leaky relu
    e_out[idx] = v;
    atomicMaxFloat(&m[(size_t)d * H + h], v);
}

// ---------------- edge pass B: exp + segment sum ----------------
__global__ void edgeB_kernel(const int* __restrict__ ei,
                             float* __restrict__ e_out,
                             const float* __restrict__ m,
                             float* __restrict__ ssum, int H) {
    int idx = blockIdx.x * blockDim.x + threadIdx.x;
    if (idx >= ETOT * H) return;
    int e = idx / H, h = idx - e * H;
    int d;
    if (e < EE) d = clampN(ei[EE + e]); else d = e - EE;
    float ex = expf(e_out[idx] - m[(size_t)d * H + h]);
    e_out[idx] = ex;
    atomicAdd(&ssum[(size_t)d * H + h], ex);
}

// ---------------- edge pass C: weighted gather + atomic scatter ----------------
// one warp per (edge, head); lane handles 4 contiguous floats (float4 load)
__global__ void edgeC_kernel(const int* __restrict__ ei,
                             const float* __restrict__ e_exp,
                             const float* __restrict__ ssum,
                             const float* __restrict__ hlin,
                             float* __restrict__ agg, int H) {
    long long gw = ((long long)blockIdx.x * blockDim.x + threadIdx.x) >> 5;
    int lane = threadIdx.x & 31;
    if (gw >= (long long)ETOT * H) return;
    int e = (int)(gw / H), h = (int)(gw - (long long)e * H);
    int s, d;
    if (e < EE) { s = clampN(ei[e]); d = clampN(ei[EE + e]); } else { s = d = e - EE; }
    float alpha = e_exp[gw] / (ssum[(size_t)d * H + h] + 1e-16f);
    const float4* hp = (const float4*)(hlin + ((size_t)s * H + h) * HID);
    float* op = agg + ((size_t)d * H + h) * HID;
    float4 v = hp[lane];
    atomicAdd(op + lane * 4 + 0, v.x * alpha);
    atomicAdd(op + lane * 4 + 1, v.y * alpha);
    atomicAdd(op + lane * 4 + 2, v.z * alpha);
    atomicAdd(op + lane * 4 + 3, v.w * alpha);
}

// ---------------- finalize: bias (+ ELU) ----------------
__global__ void finalize_kernel(const float* __restrict__ agg,
                                const float* __restrict__ bias,
                                float* __restrict__ out, int F, int do_elu) {
    int idx = blockIdx.x * blockDim.x + threadIdx.x;
    if (idx >= NN * F) return;
    int f = idx % F;
    float v = agg[idx] + bias[f];
    if (do_elu) v = (v > 0.f) ? v : expm1f(v);
    out[idx] = v;
}

// ---------------- host orchestration ----------------
static void run_layer(const float* feat_in, int K,
                      const float* W, const float* a_src, const float* a_dst,
                      const float* bias, int H, float* out_buf, int do_elu,
                      float* hlin, float* agg, float* asrc, float* adst,
                      float* m, float* s, float* e_buf, const int* ei) {
    const int F = H * HID;
    // GEMM
    {
        dim3 grid(F / 64, (NN + 63) / 64);
        gemm_kernel<<<grid, 256>>>(feat_in, W, hlin, NN, K, F);
    }
    // alpha
    {
        int warps = NN * H;
        alpha_kernel<<<(warps * 32 + 255) / 256, 256>>>(hlin, a_src, a_dst, asrc, adst, H);
    }
    // init m = -inf, s = 0, agg = 0
    {
        int nh = NN * H;
        fill_kernel<<<(nh + 255) / 256, 256>>>(m, -INFINITY, nh);
        fill_kernel<<<(nh + 255) / 256, 256>>>(s, 0.f, nh);
        int nf = NN * F;
        fill_kernel<<<(nf + 255) / 256, 256>>>(agg, 0.f, nf);
    }
    // edge passes
    {
        int nt = ETOT * H;
        edgeA_kernel<<<(nt + 255) / 256, 256>>>(ei, asrc, adst, e_buf, m, H);
        edgeB_kernel<<<(nt + 255) / 256, 256>>>(ei, e_buf, m, s, H);
        long long warps = (long long)ETOT * H;
        long long blocks = (warps * 32 + 255) / 256;
        edgeC_kernel<<<(unsigned)blocks, 256>>>(ei, e_buf, s, hlin, agg, H);
    }
    // finalize
    {
        int nf = NN * F;
        finalize_kernel<<<(nf + 255) / 256, 256>>>(agg, bias, out_buf, F, do_elu);
    }
}

extern "C" void kernel_launch(void* const* d_in, const int* in_sizes, int n_in,
                              void* d_out, int out_size) {
    const float* x       = (const float*)d_in[0];
    const int*   ei      = (const int*)d_in[1];     // int64 downcast to int32 by harness
    const float* W1      = (const float*)d_in[2];
    const float* a1_src  = (const float*)d_in[3];
    const float* a1_dst  = (const float*)d_in[4];
    const float* b1      = (const float*)d_in[5];
    const float* W2      = (const float*)d_in[6];
    const float* a2_src  = (const float*)d_in[7];
    const float* a2_dst  = (const float*)d_in[8];
    const float* b2      = (const float*)d_in[9];
    const float* W3      = (const float*)d_in[10];
    const float* a3_src  = (const float*)d_in[11];
    const float* a3_dst  = (const float*)d_in[12];
    const float* b3      = (const float*)d_in[13];

    float *feat, *hlin, *agg, *asrc, *adst, *m, *s, *e_buf;
    cudaGetSymbolAddress((void**)&feat,  g_feat);
    cudaGetSymbolAddress((void**)&hlin,  g_hlin);
    cudaGetSymbolAddress((void**)&agg,   g_agg);
    cudaGetSymbolAddress((void**)&asrc,  g_asrc);
    cudaGetSymbolAddress((void**)&adst,  g_adst);
    cudaGetSymbolAddress((void**)&m,     g_m);
    cudaGetSymbolAddress((void**)&s,     g_s);
    cudaGetSymbolAddress((void**)&e_buf, g_e);

    // Layer 1: 768 -> 4x128, concat, ELU
    run_layer(x, INC, W1, a1_src, a1_dst, b1, HEADS, feat, 1,
              hlin, agg, asrc, adst, m, s, e_buf, ei);
    // Layer 2: 512 -> 4x128, concat, ELU
    run_layer(feat, FMAX, W2, a2_src, a2_dst, b2, HEADS, feat, 1,
              hlin, agg, asrc, adst, m, s, e_buf, ei);
    // Layer 3: 512 -> 1x128, no concat (H=1 mean == identity), no ELU
    run_layer(feat, FMAX, W3, a3_src, a3_dst, b3, 1, (float*)d_out, 0,
              hlin, agg, asrc, adst, m, s, e_buf, ei);
}

// round 3
// speedup vs baseline: 2.1655x; 2.1655x over previous
#include <cuda_runtime.h>
#include <cuda_bf16.h>
#include <math.h>

// Problem constants (fixed shapes for this problem)
#define NN     20000
#define EE     400000
#define ETOT   420000      // E + N self loops
#define INC    768
#define HID    128
#define HEADS  4
#define FMAX   512         // HEADS*HID

// ---------------- device scratch (static, no allocation) ----------------
__device__ float g_feat[(size_t)NN * FMAX];
__device__ float g_hlin[(size_t)NN * FMAX];
__device__ float g_agg [(size_t)NN * FMAX];
__device__ float g_asrc[(size_t)NN * HEADS];
__device__ float g_adst[(size_t)NN * HEADS];
__device__ float g_m   [(size_t)NN * HEADS];
__device__ float g_s   [(size_t)NN * HEADS];
__device__ float g_e   [(size_t)ETOT * HEADS];

// ---------------- helpers ----------------
__device__ __forceinline__ int clampN(int v) {
    return v < 0 ? 0 : (v >= NN ? NN - 1 : v);
}

__device__ __forceinline__ void atomicMaxFloat(float* addr, float v) {
    if (v >= 0.f) atomicMax((int*)addr, __float_as_int(v));
    else          atomicMin((unsigned int*)addr, __float_as_uint(v));
}

__global__ void fill_kernel(float* __restrict__ p, float v, int n) {
    int i = blockIdx.x * blockDim.x + threadIdx.x;
    if (i < n) p[i] = v;
}

// ---------------- SGEMM: C[M,N] = A[M,K] @ B[K,N], fp32 ----------------
// BM=BN=128, BK=8, 256 threads, 8x8 micro-tile, double-buffered smem.
// Requires: N % 128 == 0, K % 8 == 0 (true here: N in {512,128}, K in {768,512}).
__global__ void __launch_bounds__(256, 2)
sgemm_kernel(const float* __restrict__ A,
             const float* __restrict__ B,
             float* __restrict__ C,
             int M, int K, int N) {
    __shared__ float As[2][8][128];
    __shared__ float Bs[2][8][128];

    const int tid  = threadIdx.x;
    const int row0 = blockIdx.y * 128;
    const int col0 = blockIdx.x * 128;
    const int tx   = tid & 15;       // 0..15 (column group)
    const int ty   = tid >> 4;       // 0..15 (row group)

    // A loader: one float4 per thread: row = tid>>1 (0..127), col4 = (tid&1)*4
    const int arow = tid >> 1;
    const int acol = (tid & 1) * 4;
    const int a_grow = min(row0 + arow, M - 1);
    // B loader: one float4 per thread: row = tid>>5 (0..7), col = (tid&31)*4
    const int brow = tid >> 5;
    const int bcol = (tid & 31) * 4;

    float acc[8][8];
#pragma unroll
    for (int i = 0; i < 8; i++)
#pragma unroll
        for (int j = 0; j < 8; j++) acc[i][j] = 0.f;

    const int nIter = K / 8;

    // prologue: load tile 0
    float4 av = *(const float4*)(A + (size_t)a_grow * K + acol);
    float4 bv = *(const float4*)(B + (size_t)brow * N + col0 + bcol);
    As[0][acol + 0][arow] = av.x;
    As[0][acol + 1][arow] = av.y;
    As[0][acol + 2][arow] = av.z;
    As[0][acol + 3][arow] = av.w;
    *(float4*)&Bs[0][brow][bcol] = bv;
    __syncthreads();

    for (int it = 0; it < nIter; it++) {
        const int cur = it & 1;
        const int nxt = cur ^ 1;
        if (it + 1 < nIter) {
            const int k0 = (it + 1) * 8;
            av = *(const float4*)(A + (size_t)a_grow * K + k0 + acol);
            bv = *(const float4*)(B + (size_t)(k0 + brow) * N + col0 + bcol);
        }
#pragma unroll
        for (int k = 0; k < 8; k++) {
            float a_frag[8], b_frag[8];
            *(float4*)&a_frag[0] = *(const float4*)&As[cur][k][ty * 8];
            *(float4*)&a_frag[4] = *(const float4*)&As[cur][k][ty * 8 + 4];
            *(float4*)&b_frag[0] = *(const float4*)&Bs[cur][k][tx * 8];
            *(float4*)&b_frag[4] = *(const float4*)&Bs[cur][k][tx * 8 + 4];
#pragma unroll
            for (int i = 0; i < 8; i++)
#pragma unroll
                for (int j = 0; j < 8; j++)
                    acc[i][j] = fmaf(a_frag[i], b_frag[j], acc[i][j]);
        }
        if (it + 1 < nIter) {
            As[nxt][acol + 0][arow] = av.x;
            As[nxt][acol + 1][arow] = av.y;
            As[nxt][acol + 2][arow] = av.z;
            As[nxt][acol + 3][arow] = av.w;
            *(float4*)&Bs[nxt][brow][bcol] = bv;
            __syncthreads();
        }
    }

#pragma unroll
    for (int i = 0; i < 8; i++) {
        int gr = row0 + ty * 8 + i;
        if (gr < M) {
            float4 o0 = make_float4(acc[i][0], acc[i][1], acc[i][2], acc[i][3]);
            float4 o1 = make_float4(acc[i][4], acc[i][5], acc[i][6], acc[i][7]);
            *(float4*)(C + (size_t)gr * N + col0 + tx * 8)     = o0;
            *(float4*)(C + (size_t)gr * N + col0 + tx * 8 + 4) = o1;
        }
    }
}

// ---------------- alpha: per (node, head) warp dot products ----------------
__global__ void alpha_kernel(const float* __restrict__ hlin,
                             const float* __restrict__ a_src,
                             const float* __restrict__ a_dst,
                             float* __restrict__ asrc,
                             float* __restrict__ adst, int H) {
    int gw = (blockIdx.x * blockDim.x + threadIdx.x) >> 5;
    int lane = threadIdx.x & 31;
    if (gw >= NN * H) return;
    int n = gw / H, h = gw - n * H;
    const float* hp = hlin + ((size_t)n * H + h) * HID;
    const float* as = a_src + h * HID;
    const float* ad = a_dst + h * HID;
    float ss = 0.f, sd = 0.f;
#pragma unroll
    for (int i = 0; i < HID / 32; i++) {
        float v = hp[lane + i * 32];
        ss = fmaf(v, as[lane + i * 32], ss);
        sd = fmaf(v, ad[lane + i * 32], sd);
    }
#pragma unroll
    for (int o = 16; o; o >>= 1) {
        ss += __shfl_xor_sync(0xffffffffu, ss, o);
        sd += __shfl_xor_sync(0xffffffffu, sd, o);
    }
    if (lane == 0) { asrc[gw] = ss; adst[gw] = sd; }
}

// ---------------- edge pass A: logits + segment max ----------------
__global__ void edgeA_kernel(const int* __restrict__ ei,
                             const float* __restrict__ asrc,
                             const float* __restrict__ adst,
                             float* __restrict__ e_out,
                             float* __restrict__ m, int H) {
    int idx = blockIdx.x * blockDim.x + threadIdx.x;
    if (idx >= ETOT * H) return;
    int e = idx / H, h = idx - e * H;
    int s, d;
    if (e < EE) { s = clampN(ei[e]); d = clampN(ei[EE + e]); } else { s = d = e - EE; }
    float v = asrc[(size_t)s * H + h] + adst[(size_t)d * H + h];
    v = (v > 0.f) ? v : 0.2f * v;   // leaky relu
    e_out[idx] = v;
    atomicMaxFloat(&m[(size_t)d * H + h], v);
}

// ---------------- edge pass B: exp + segment sum ----------------
__global__ void edgeB_kernel(const int* __restrict__ ei,
                             float* __restrict__ e_out,
                             const float* __restrict__ m,
                             float* __restrict__ ssum, int H) {
    int idx = blockIdx.x * blockDim.x + threadIdx.x;
    if (idx >= ETOT * H) return;
    int e = idx / H, h = idx - e * H;
    int d;
    if (e < EE) d = clampN(ei[EE + e]); else d = e - EE;
    float ex = expf(e_out[idx] - m[(size_t)d * H + h]);
    e_out[idx] = ex;
    atomicAdd(&ssum[(size_t)d * H + h], ex);
}

// ---------------- edge pass C: weighted gather + vector reduction scatter ----
// one warp per (edge, head); lane handles 4 contiguous floats (float4 load),
// scattered via a single red.global.add.v4.f32.
__global__ void edgeC_kernel(const int* __restrict__ ei,
                             const float* __restrict__ e_exp,
                             const float* __restrict__ ssum,
                             const float* __restrict__ hlin,
                             float* __restrict__ agg, int H) {
    long long gw = ((long long)blockIdx.x * blockDim.x + threadIdx.x) >> 5;
    int lane = threadIdx.x & 31;
    if (gw >= (long long)ETOT * H) return;
    int e = (int)(gw / H), h = (int)(gw - (long long)e * H);
    int s, d;
    if (e < EE) { s = clampN(ei[e]); d = clampN(ei[EE + e]); } else { s = d = e - EE; }
    float alpha = e_exp[gw] / (ssum[(size_t)d * H + h] + 1e-16f);
    const float4* hp = (const float4*)(hlin + ((size_t)s * H + h) * HID);
    float* op = agg + ((size_t)d * H + h) * HID + lane * 4;
    float4 v = hp[lane];
    asm volatile("red.global.add.v4.f32 [%0], {%1, %2, %3, %4};"
                 :: "l"(op), "f"(v.x * alpha), "f"(v.y * alpha),
                    "f"(v.z * alpha), "f"(v.w * alpha)
                 : "memory");
}

// ---------------- finalize: bias (+ ELU) ----------------
__global__ void finalize_kernel(const float* __restrict__ agg,
                                const float* __restrict__ bias,
                                float* __restrict__ out, int F, int do_elu) {
    int idx = blockIdx.x * blockDim.x + threadIdx.x;
    if (idx >= NN * F) return;
    int f = idx % F;
    float v = agg[idx] + bias[f];
    if (do_elu) v = (v > 0.f) ? v : expm1f(v);
    out[idx] = v;
}

// ---------------- host orchestration ----------------
static void run_layer(const float* feat_in, int K,
                      const float* W, const float* a_src, const float* a_dst,
                      const float* bias, int H, float* out_buf, int do_elu,
                      float* hlin, float* agg, float* asrc, float* adst,
                      float* m, float* s, float* e_buf, const int* ei) {
    const int F = H * HID;
    // GEMM
    {
        dim3 grid(F / 128, (NN + 127) / 128);
        sgemm_kernel<<<grid, 256>>>(feat_in, W, hlin, NN, K, F);
    }
    // alpha
    {
        int warps = NN * H;
        alpha_kernel<<<(warps * 32 + 255) / 256, 256>>>(hlin, a_src, a_dst, asrc, adst, H);
    }
    // init m = -inf, s = 0, agg = 0
    {
        int nh = NN * H;
        fill_kernel<<<(nh + 255) / 256, 256>>>(m, -INFINITY, nh);
        fill_kernel<<<(nh + 255) / 256, 256>>>(s, 0.f, nh);
        int nf = NN * F;
        fill_kernel<<<(nf + 255) / 256, 256>>>(agg, 0.f, nf);
    }
    // edge passes
    {
        int nt = ETOT * H;
        edgeA_kernel<<<(nt + 255) / 256, 256>>>(ei, asrc, adst, e_buf, m, H);
        edgeB_kernel<<<(nt + 255) / 256, 256>>>(ei, e_buf, m, s, H);
        long long warps = (long long)ETOT * H;
        long long blocks = (warps * 32 + 255) / 256;
        edgeC_kernel<<<(unsigned)blocks, 256>>>(ei, e_buf, s, hlin, agg, H);
    }
    // finalize
    {
        int nf = NN * F;
        finalize_kernel<<<(nf + 255) / 256, 256>>>(agg, bias, out_buf, F, do_elu);
    }
}

extern "C" void kernel_launch(void* const* d_in, const int* in_sizes, int n_in,
                              void* d_out, int out_size) {
    const float* x       = (const float*)d_in[0];
    const int*   ei      = (const int*)d_in[1];     // int64 downcast to int32 by harness
    const float* W1      = (const float*)d_in[2];
    const float* a1_src  = (const float*)d_in[3];
    const float* a1_dst  = (const float*)d_in[4];
    const float* b1      = (const float*)d_in[5];
    const float* W2      = (const float*)d_in[6];
    const float* a2_src  = (const float*)d_in[7];
    const float* a2_dst  = (const float*)d_in[8];
    const float* b2      = (const float*)d_in[9];
    const float* W3      = (const float*)d_in[10];
    const float* a3_src  = (const float*)d_in[11];
    const float* a3_dst  = (const float*)d_in[12];
    const float* b3      = (const float*)d_in[13];

    float *feat, *hlin, *agg, *asrc, *adst, *m, *s, *e_buf;
    cudaGetSymbolAddress((void**)&feat,  g_feat);
    cudaGetSymbolAddress((void**)&hlin,  g_hlin);
    cudaGetSymbolAddress((void**)&agg,   g_agg);
    cudaGetSymbolAddress((void**)&asrc,  g_asrc);
    cudaGetSymbolAddress((void**)&adst,  g_adst);
    cudaGetSymbolAddress((void**)&m,     g_m);
    cudaGetSymbolAddress((void**)&s,     g_s);
    cudaGetSymbolAddress((void**)&e_buf, g_e);

    // Layer 1: 768 -> 4x128, concat, ELU
    run_layer(x, INC, W1, a1_src, a1_dst, b1, HEADS, feat, 1,
              hlin, agg, asrc, adst, m, s, e_buf, ei);
    // Layer 2: 512 -> 4x128, concat, ELU
    run_layer(feat, FMAX, W2, a2_src, a2_dst, b2, HEADS, feat, 1,
              hlin, agg, asrc, adst, m, s, e_buf, ei);
    // Layer 3: 512 -> 1x128, no concat (H=1 mean == identity), no ELU
    run_layer(feat, FMAX, W3, a3_src, a3_dst, b3, 1, (float*)d_out, 0,
              hlin, agg, asrc, adst, m, s, e_buf, ei);
}

// round 5
// speedup vs baseline: 2.6667x; 1.2315x over previous
#include <cuda_runtime.h>
#include <cuda_bf16.h>
#include <math.h>
#include <stdint.h>

// Problem constants
#define NN     20000
#define EE     400000
#define ETOT   420000
#define INC    768
#define HID    128
#define HEADS  4
#define FMAX   512

// ---------------- device scratch ----------------
__device__ float g_feat[(size_t)NN * FMAX];
__device__ float g_hlin[(size_t)NN * FMAX];
__device__ float g_agg [(size_t)NN * FMAX];
__device__ float g_asrc[(size_t)NN * HEADS];
__device__ float g_adst[(size_t)NN * HEADS];
__device__ float g_m   [(size_t)NN * HEADS];
__device__ float g_s   [(size_t)NN * HEADS];
__device__ float g_e   [(size_t)ETOT * HEADS];
__device__ __nv_bfloat16 g_ah [(size_t)NN * INC];
__device__ __nv_bfloat16 g_al [(size_t)NN * INC];
__device__ __nv_bfloat16 g_wth[(size_t)FMAX * INC];
__device__ __nv_bfloat16 g_wtl[(size_t)FMAX * INC];

// ---------------- misc helpers ----------------
__device__ __forceinline__ int clampN(int v) { return v < 0 ? 0 : (v >= NN ? NN - 1 : v); }
__device__ __forceinline__ void atomicMaxFloat(float* addr, float v) {
    if (v >= 0.f) atomicMax((int*)addr, __float_as_int(v));
    else          atomicMin((unsigned int*)addr, __float_as_uint(v));
}

__global__ void fill_kernel(float* __restrict__ p, float v, int n) {
    int i = blockIdx.x * blockDim.x + threadIdx.x;
    if (i < n) p[i] = v;
}

// ---------------- fp32 -> bf16 hi/lo split ----------------
__global__ void split_kernel(const float* __restrict__ x,
                             __nv_bfloat16* __restrict__ hi,
                             __nv_bfloat16* __restrict__ lo, int n) {
    int i = blockIdx.x * blockDim.x + threadIdx.x;
    if (i >= n) return;
    float v = x[i];
    __nv_bfloat16 h = __float2bfloat16(v);
    hi[i] = h;
    lo[i] = __float2bfloat16(v - __bfloat162float(h));
}

// W [K,N] fp32 -> Wt hi/lo [N,K] bf16 (transposed: K-major rows per output col)
__global__ void splitT_kernel(const float* __restrict__ W,
                              __nv_bfloat16* __restrict__ hi,
                              __nv_bfloat16* __restrict__ lo, int K, int Nn) {
    int i = blockIdx.x * blockDim.x + threadIdx.x;
    if (i >= K * Nn) return;
    int k = i / Nn, n = i - k * Nn;
    float v = W[i];
    __nv_bfloat16 h = __float2bfloat16(v);
    size_t o = (size_t)n * K + k;
    hi[o] = h;
    lo[o] = __float2bfloat16(v - __bfloat162float(h));
}

// ---------------- HMMA bf16 GEMM: C[M,N] = A[M,K] @ B^T (B stored [N,K]) ----
// 3-product split: Ah*Bh + Ah*Bl + Al*Bh, fp32 accumulation.
// BM=BN=128, BK=32, 8 warps (2x4), warp tile 64x32, mma.m16n8k16.
#define SPAD 40   // bf16 elements per padded smem row (conflict-free fragment loads)

__device__ __forceinline__ void mma_bf16(float* c, const uint32_t* a, const uint32_t* b) {
    asm volatile("mma.sync.aligned.m16n8k16.row.col.f32.bf16.bf16.f32 "
                 "{%0,%1,%2,%3}, {%4,%5,%6,%7}, {%8,%9}, {%0,%1,%2,%3};"
                 : "+f"(c[0]), "+f"(c[1]), "+f"(c[2]), "+f"(c[3])
                 : "r"(a[0]), "r"(a[1]), "r"(a[2]), "r"(a[3]),
                   "r"(b[0]), "r"(b[1]));
}

__global__ void __launch_bounds__(256)
hgemm_kernel(const __nv_bfloat16* __restrict__ Ah,
             const __nv_bfloat16* __restrict__ Al,
             const __nv_bfloat16* __restrict__ Bh,
             const __nv_bfloat16* __restrict__ Bl,
             float* __restrict__ C, int M, int K, int Nn) {
    __shared__ __nv_bfloat16 sAh[128 * SPAD];
    __shared__ __nv_bfloat16 sAl[128 * SPAD];
    __shared__ __nv_bfloat16 sBh[128 * SPAD];
    __shared__ __nv_bfloat16 sBl[128 * SPAD];

    const int tid  = threadIdx.x;
    const int lane = tid & 31;
    const int wid  = tid >> 5;
    const int wm   = (wid >> 2) * 64;    // warp row offset (0/64)
    const int wn   = (wid & 3) * 32;     // warp col offset (0/32/64/96)
    const int row0 = blockIdx.y * 128;
    const int col0 = blockIdx.x * 128;
    const int g4   = lane >> 2;          // 0..7
    const int t4   = lane & 3;           // 0..3

    float acc[4][4][4];
#pragma unroll
    for (int a = 0; a < 4; a++)
#pragma unroll
        for (int b = 0; b < 4; b++)
#pragma unroll
            for (int c = 0; c < 4; c++) acc[a][b][c] = 0.f;

    for (int kc0 = 0; kc0 < K; kc0 += 32) {
        __syncthreads();
        // stage 4 tiles of [128 rows x 32 bf16]; each thread moves 2 uint4 per tile
#pragma unroll
        for (int t = 0; t < 2; t++) {
            int idx = tid + t * 256;             // 0..511
            int r = idx >> 2, c = idx & 3;       // row, 8-elem group
            int gra = min(row0 + r, M - 1);
            const uint4* pah = (const uint4*)(Ah + (size_t)gra * K + kc0);
            const uint4* pal = (const uint4*)(Al + (size_t)gra * K + kc0);
            *(uint4*)&sAh[r * SPAD + c * 8] = pah[c];
            *(uint4*)&sAl[r * SPAD + c * 8] = pal[c];
            int grb = col0 + r;
            const uint4* pbh = (const uint4*)(Bh + (size_t)grb * K + kc0);
            const uint4* pbl = (const uint4*)(Bl + (size_t)grb * K + kc0);
            *(uint4*)&sBh[r * SPAD + c * 8] = pbh[c];
            *(uint4*)&sBl[r * SPAD + c * 8] = pbl[c];
        }
        __syncthreads();

#pragma unroll
        for (int ks = 0; ks < 32; ks += 16) {
            const int kb = ks + t4 * 2;
            uint32_t bh[4][2], bl[4][2];
#pragma unroll
            for (int nt = 0; nt < 4; nt++) {
                int n0 = wn + nt * 8 + g4;
                bh[nt][0] = *(const uint32_t*)&sBh[n0 * SPAD + kb];
                bh[nt][1] = *(const uint32_t*)&sBh[n0 * SPAD + kb + 8];
                bl[nt][0] = *(const uint32_t*)&sBl[n0 * SPAD + kb];
                bl[nt][1] = *(const uint32_t*)&sBl[n0 * SPAD + kb + 8];
            }
#pragma unroll
            for (int mt = 0; mt < 4; mt++) {
                int m0 = wm + mt * 16 + g4;
                uint32_t ah[4], al[4];
                ah[0] = *(const uint32_t*)&sAh[m0 * SPAD + kb];
                ah[1] = *(const uint32_t*)&sAh[(m0 + 8) * SPAD + kb];
                ah[2] = *(const uint32_t*)&sAh[m0 * SPAD + kb + 8];
                ah[3] = *(const uint32_t*)&sAh[(m0 + 8) * SPAD + kb + 8];
                al[0] = *(const uint32_t*)&sAl[m0 * SPAD + kb];
                al[1] = *(const uint32_t*)&sAl[(m0 + 8) * SPAD + kb];
                al[2] = *(const uint32_t*)&sAl[m0 * SPAD + kb + 8];
                al[3] = *(const uint32_t*)&sAl[(m0 + 8) * SPAD + kb + 8];
#pragma unroll
                for (int nt = 0; nt < 4; nt++) {
                    mma_bf16(acc[mt][nt], ah, bh[nt]);
                    mma_bf16(acc[mt][nt], ah, bl[nt]);
                    mma_bf16(acc[mt][nt], al, bh[nt]);
                }
            }
        }
    }

    // epilogue: direct register stores (float2 per row fragment)
#pragma unroll
    for (int mt = 0; mt < 4; mt++) {
#pragma unroll
        for (int nt = 0; nt < 4; nt++) {
            int gm = row0 + wm + mt * 16 + g4;
            int gc = col0 + wn + nt * 8 + t4 * 2;
            if (gm < M) {
                float2 v0 = make_float2(acc[mt][nt][0], acc[mt][nt][1]);
                *(float2*)&C[(size_t)gm * Nn + gc] = v0;
            }
            if (gm + 8 < M) {
                float2 v1 = make_float2(acc[mt][nt][2], acc[mt][nt][3]);
                *(float2*)&C[(size_t)(gm + 8) * Nn + gc] = v1;
            }
        }
    }
}

// ---------------- alpha: per (node, head) warp dot products ----------------
__global__ void alpha_kernel(const float* __restrict__ hlin,
                             const float* __restrict__ a_src,
                             const float* __restrict__ a_dst,
                             float* __restrict__ asrc,
                             float* __restrict__ adst, int H) {
    int gw = (blockIdx.x * blockDim.x + threadIdx.x) >> 5;
    int lane = threadIdx.x & 31;
    if (gw >= NN * H) return;
    int n = gw / H, h = gw - n * H;
    const float* hp = hlin + ((size_t)n * H + h) * HID;
    const float* as = a_src + h * HID;
    const float* ad = a_dst + h * HID;
    float ss = 0.f, sd = 0.f;
#pragma unroll
    for (int i = 0; i < HID / 32; i++) {
        float v = hp[lane + i * 32];
        ss = fmaf(v, as[lane + i * 32], ss);
        sd = fmaf(v, ad[lane + i * 32], sd);
    }
#pragma unroll
    for (int o = 16; o; o >>= 1) {
        ss += __shfl_xor_sync(0xffffffffu, ss, o);
        sd += __shfl_xor_sync(0xffffffffu, sd, o);
    }
    if (lane == 0) { asrc[gw] = ss; adst[gw] = sd; }
}

// ---------------- edge passes ----------------
__global__ void edgeA_kernel(const int* __restrict__ ei,
                             const float* __restrict__ asrc,
                             const float* __restrict__ adst,
                             float* __restrict__ e_out,
                             float* __restrict__ m, int H) {
    int idx = blockIdx.x * blockDim.x + threadIdx.x;
    if (idx >= ETOT * H) return;
    int e = idx / H, h = idx - e * H;
    int s, d;
    if (e < EE) { s = clampN(ei[e]); d = clampN(ei[EE + e]); } else { s = d = e - EE; }
    float v = asrc[(size_t)s * H + h] + adst[(size_t)d * H + h];
    v = (v > 0.f) ? v : 0.2f * v;
    e_out[idx] = v;
    atomicMaxFloat(&m[(size_t)d * H + h], v);
}

__global__ void edgeB_kernel(const int* __restrict__ ei,
                             float* __restrict__ e_out,
                             const float* __restrict__ m,
                             float* __restrict__ ssum, int H) {
    int idx = blockIdx.x * blockDim.x + threadIdx.x;
    if (idx >= ETOT * H) return;
    int e = idx / H, h = idx - e * H;
    int d;
    if (e < EE) d = clampN(ei[EE + e]); else d = e - EE;
    float ex = expf(e_out[idx] - m[(size_t)d * H + h]);
    e_out[idx] = ex;
    atomicAdd(&ssum[(size_t)d * H + h], ex);
}

__global__ void edgeC_kernel(const int* __restrict__ ei,
                             const float* __restrict__ e_exp,
                             const float* __restrict__ ssum,
                             const float* __restrict__ hlin,
                             float* __restrict__ agg, int H) {
    long long gw = ((long long)blockIdx.x * blockDim.x + threadIdx.x) >> 5;
    int lane = threadIdx.x & 31;
    if (gw >= (long long)ETOT * H) return;
    int e = (int)(gw / H), h = (int)(gw - (long long)e * H);
    int s, d;
    if (e < EE) { s = clampN(ei[e]); d = clampN(ei[EE + e]); } else { s = d = e - EE; }
    float alpha = e_exp[gw] / (ssum[(size_t)d * H + h] + 1e-16f);
    const float4* hp = (const float4*)(hlin + ((size_t)s * H + h) * HID);
    float* op = agg + ((size_t)d * H + h) * HID + lane * 4;
    float4 v = hp[lane];
    asm volatile("red.global.add.v4.f32 [%0], {%1, %2, %3, %4};"
                 :: "l"(op), "f"(v.x * alpha), "f"(v.y * alpha),
                    "f"(v.z * alpha), "f"(v.w * alpha)
                 : "memory");
}

__global__ void finalize_kernel(const float* __restrict__ agg,
                                const float* __restrict__ bias,
                                float* __restrict__ out, int F, int do_elu) {
    int idx = blockIdx.x * blockDim.x + threadIdx.x;
    if (idx >= NN * F) return;
    int f = idx % F;
    float v = agg[idx] + bias[f];
    if (do_elu) v = (v > 0.f) ? v : expm1f(v);
    out[idx] = v;
}

// ---------------- host orchestration ----------------
static void run_layer(const float* feat_in, int K,
                      const float* W, const float* a_src, const float* a_dst,
                      const float* bias, int H, float* out_buf, int do_elu,
                      float* hlin, float* agg, float* asrc, float* adst,
                      float* m, float* s, float* e_buf, const int* ei,
                      __nv_bfloat16* ah, __nv_bfloat16* al,
                      __nv_bfloat16* wth, __nv_bfloat16* wtl) {
    const int F = H * HID;
    // split inputs + weights to bf16 hi/lo
    {
        int na = NN * K;
        split_kernel<<<(na + 255) / 256, 256>>>(feat_in, ah, al, na);
        int nw = K * F;
        splitT_kernel<<<(nw + 255) / 256, 256>>>(W, wth, wtl, K, F);
    }
    // tensor-core GEMM (HMMA)
    {
        dim3 grid(F / 128, (NN + 127) / 128);
        hgemm_kernel<<<grid, 256>>>(ah, al, wth, wtl, hlin, NN, K, F);
    }
    // alpha
    {
        int warps = NN * H;
        alpha_kernel<<<(warps * 32 + 255) / 256, 256>>>(hlin, a_src, a_dst, asrc, adst, H);
    }
    // init m = -inf, s = 0, agg = 0
    {
        int nh = NN * H;
        fill_kernel<<<(nh + 255) / 256, 256>>>(m, -INFINITY, nh);
        fill_kernel<<<(nh + 255) / 256, 256>>>(s, 0.f, nh);
        int nf = NN * F;
        fill_kernel<<<(nf + 255) / 256, 256>>>(agg, 0.f, nf);
    }
    // edge passes
    {
        int nt = ETOT * H;
        edgeA_kernel<<<(nt + 255) / 256, 256>>>(ei, asrc, adst, e_buf, m, H);
        edgeB_kernel<<<(nt + 255) / 256, 256>>>(ei, e_buf, m, s, H);
        long long warps = (long long)ETOT * H;
        long long blocks = (warps * 32 + 255) / 256;
        edgeC_kernel<<<(unsigned)blocks, 256>>>(ei, e_buf, s, hlin, agg, H);
    }
    // finalize
    {
        int nf = NN * F;
        finalize_kernel<<<(nf + 255) / 256, 256>>>(agg, bias, out_buf, F, do_elu);
    }
}

extern "C" void kernel_launch(void* const* d_in, const int* in_sizes, int n_in,
                              void* d_out, int out_size) {
    const float* x       = (const float*)d_in[0];
    const int*   ei      = (const int*)d_in[1];
    const float* W1      = (const float*)d_in[2];
    const float* a1_src  = (const float*)d_in[3];
    const float* a1_dst  = (const float*)d_in[4];
    const float* b1      = (const float*)d_in[5];
    const float* W2      = (const float*)d_in[6];
    const float* a2_src  = (const float*)d_in[7];
    const float* a2_dst  = (const float*)d_in[8];
    const float* b2      = (const float*)d_in[9];
    const float* W3      = (const float*)d_in[10];
    const float* a3_src  = (const float*)d_in[11];
    const float* a3_dst  = (const float*)d_in[12];
    const float* b3      = (const float*)d_in[13];

    float *feat, *hlin, *agg, *asrc, *adst, *m, *s, *e_buf;
    __nv_bfloat16 *ah, *al, *wth, *wtl;
    cudaGetSymbolAddress((void**)&feat,  g_feat);
    cudaGetSymbolAddress((void**)&hlin,  g_hlin);
    cudaGetSymbolAddress((void**)&agg,   g_agg);
    cudaGetSymbolAddress((void**)&asrc,  g_asrc);
    cudaGetSymbolAddress((void**)&adst,  g_adst);
    cudaGetSymbolAddress((void**)&m,     g_m);
    cudaGetSymbolAddress((void**)&s,     g_s);
    cudaGetSymbolAddress((void**)&e_buf, g_e);
    cudaGetSymbolAddress((void**)&ah,    g_ah);
    cudaGetSymbolAddress((void**)&al,    g_al);
    cudaGetSymbolAddress((void**)&wth,   g_wth);
    cudaGetSymbolAddress((void**)&wtl,   g_wtl);

    run_layer(x, INC, W1, a1_src, a1_dst, b1, HEADS, feat, 1,
              hlin, agg, asrc, adst, m, s, e_buf, ei, ah, al, wth, wtl);
    run_layer(feat, FMAX, W2, a2_src, a2_dst, b2, HEADS, feat, 1,
              hlin, agg, asrc, adst, m, s, e_buf, ei, ah, al, wth, wtl);
    run_layer(feat, FMAX, W3, a3_src, a3_dst, b3, 1, (float*)d_out, 0,
              hlin, agg, asrc, adst, m, s, e_buf, ei, ah, al, wth, wtl);
}

// round 6
// speedup vs baseline: 3.0395x; 1.1398x over previous
#include <cuda_runtime.h>
#include <cuda_bf16.h>
#include <math.h>
#include <stdint.h>

// Problem constants
#define NN     20000
#define EE     400000
#define ETOT   420000
#define INC    768
#define HID    128
#define HEADS  4
#define FMAX   512

// ---------------- device scratch ----------------
__device__ float g_hlin[(size_t)NN * FMAX];
__device__ float g_agg [(size_t)NN * FMAX];
__device__ float g_asrc[(size_t)NN * HEADS];
__device__ float g_adst[(size_t)NN * HEADS];
__device__ float g_m   [(size_t)NN * HEADS];
__device__ float g_s   [(size_t)NN * HEADS];
__device__ float g_e   [(size_t)ETOT * HEADS];
__device__ __nv_bfloat16 g_ah [(size_t)NN * INC];
__device__ __nv_bfloat16 g_al [(size_t)NN * INC];
__device__ __nv_bfloat16 g_wth[(size_t)FMAX * INC];
__device__ __nv_bfloat16 g_wtl[(size_t)FMAX * INC];

// ---------------- misc helpers ----------------
__device__ __forceinline__ int clampN(int v) { return v < 0 ? 0 : (v >= NN ? NN - 1 : v); }
__device__ __forceinline__ void atomicMaxFloat(float* addr, float v) {
    if (v >= 0.f) atomicMax((int*)addr, __float_as_int(v));
    else          atomicMin((unsigned int*)addr, __float_as_uint(v));
}
__device__ __forceinline__ uint32_t smem_u32(const void* p) {
    uint32_t a;
    asm("{ .reg .u64 t; cvta.to.shared.u64 t, %1; cvt.u32.u64 %0, t; }" : "=r"(a) : "l"(p));
    return a;
}

__global__ void fill_kernel(float* __restrict__ p, float v, int n) {
    int i = blockIdx.x * blockDim.x + threadIdx.x;
    if (i < n) p[i] = v;
}
// init m=-inf and s=0 in one launch
__global__ void init_ms_kernel(float* __restrict__ m, float* __restrict__ s, int n) {
    int i = blockIdx.x * blockDim.x + threadIdx.x;
    if (i < n) { m[i] = -INFINITY; s[i] = 0.f; }
}

// ---------------- fp32 -> bf16 hi/lo split ----------------
__global__ void split_kernel(const float* __restrict__ x,
                             __nv_bfloat16* __restrict__ hi,
                             __nv_bfloat16* __restrict__ lo, int n) {
    int i = blockIdx.x * blockDim.x + threadIdx.x;
    if (i >= n) return;
    float v = x[i];
    __nv_bfloat16 h = __float2bfloat16(v);
    hi[i] = h;
    lo[i] = __float2bfloat16(v - __bfloat162float(h));
}

// W [K,N] fp32 -> Wt hi/lo [N,K] bf16 (transposed)
__global__ void splitT_kernel(const float* __restrict__ W,
                              __nv_bfloat16* __restrict__ hi,
                              __nv_bfloat16* __restrict__ lo, int K, int Nn) {
    int i = blockIdx.x * blockDim.x + threadIdx.x;
    if (i >= K * Nn) return;
    int k = i / Nn, n = i - k * Nn;
    float v = W[i];
    __nv_bfloat16 h = __float2bfloat16(v);
    size_t o = (size_t)n * K + k;
    hi[o] = h;
    lo[o] = __float2bfloat16(v - __bfloat162float(h));
}

// ---------------- HMMA bf16 GEMM with cp.async + ldmatrix ----------------
// C[M,N] = A[M,K] @ B^T (B stored [N,K]); 3-product split Ah*Bh + Ah*Bl + Al*Bh.
// BM=BN=128, BK=16, 8 warps (2x4), warp tile 64x32, 2-stage cp.async pipeline.
#define SPAD 24   // bf16 per padded smem row (48B stride: conflict-free mod 128)
#define TILE_ELEMS (128 * SPAD)

__device__ __forceinline__ void mma_bf16(float* c, const uint32_t* a, const uint32_t* b) {
    asm volatile("mma.sync.aligned.m16n8k16.row.col.f32.bf16.bf16.f32 "
                 "{%0,%1,%2,%3}, {%4,%5,%6,%7}, {%8,%9}, {%0,%1,%2,%3};"
                 : "+f"(c[0]), "+f"(c[1]), "+f"(c[2]), "+f"(c[3])
                 : "r"(a[0]), "r"(a[1]), "r"(a[2]), "r"(a[3]),
                   "r"(b[0]), "r"(b[1]));
}
#define LDM_X4(r0, r1, r2, r3, a) \
    asm volatile("ldmatrix.sync.aligned.m8n8.x4.shared.b16 {%0,%1,%2,%3}, [%4];" \
                 : "=r"(r0), "=r"(r1), "=r"(r2), "=r"(r3) : "r"(a))
#define CP_ASYNC16(dst, src) \
    asm volatile("cp.async.ca.shared.global [%0], [%1], 16;" :: "r"(dst), "l"(src))

__global__ void __launch_bounds__(256)
hgemm_kernel(const __nv_bfloat16* __restrict__ Ah,
             const __nv_bfloat16* __restrict__ Al,
             const __nv_bfloat16* __restrict__ Bh,
             const __nv_bfloat16* __restrict__ Bl,
             float* __restrict__ C, int M, int K, int Nn) {
    __shared__ __nv_bfloat16 sm[2 * 4 * TILE_ELEMS];   // exactly 48KB

    const int tid  = threadIdx.x;
    const int lane = tid & 31;
    const int wid  = tid >> 5;
    const int wm   = (wid >> 2) * 64;
    const int wn   = (wid & 3) * 32;
    const int row0 = blockIdx.y * 128;
    const int col0 = blockIdx.x * 128;
    const int g4   = lane >> 2;
    const int t4   = lane & 3;

    // ldmatrix per-lane offsets (elements)
    const int a_off = (lane & 15) * SPAD + (lane >> 4) * 8;
    const int b_off = ((lane & 7) + ((lane & 16) ? 8 : 0)) * SPAD + ((lane & 8) ? 8 : 0);

    // loader indices: one 16B per tile per thread
    const int lr = tid >> 1;            // row 0..127
    const int lc = (tid & 1) * 8;       // element col 0 / 8

    float acc[4][4][4];
#pragma unroll
    for (int a = 0; a < 4; a++)
#pragma unroll
        for (int b = 0; b < 4; b++)
#pragma unroll
            for (int c = 0; c < 4; c++) acc[a][b][c] = 0.f;

    const int nCh = K >> 4;
    const int gra = min(row0 + lr, M - 1);
    const int grb = col0 + lr;

    // issue cp.async loads for chunk ch into stage ch&1
#define ISSUE(ch) do {                                                          \
    __nv_bfloat16* sb_ = sm + ((ch) & 1) * 4 * TILE_ELEMS;                      \
    int kc0_ = (ch) << 4;                                                       \
    uint32_t d0 = smem_u32(sb_ + 0 * TILE_ELEMS + lr * SPAD + lc);              \
    uint32_t d1 = smem_u32(sb_ + 1 * TILE_ELEMS + lr * SPAD + lc);              \
    uint32_t d2 = smem_u32(sb_ + 2 * TILE_ELEMS + lr * SPAD + lc);              \
    uint32_t d3 = smem_u32(sb_ + 3 * TILE_ELEMS + lr * SPAD + lc);              \
    CP_ASYNC16(d0, Ah + (size_t)gra * K + kc0_ + lc);                           \
    CP_ASYNC16(d1, Al + (size_t)gra * K + kc0_ + lc);                           \
    CP_ASYNC16(d2, Bh + (size_t)grb * K + kc0_ + lc);                           \
    CP_ASYNC16(d3, Bl + (size_t)grb * K + kc0_ + lc);                           \
    asm volatile("cp.async.commit_group;");                                     \
} while (0)

    ISSUE(0);
    for (int ch = 0; ch < nCh; ch++) {
        if (ch + 1 < nCh) {
            ISSUE(ch + 1);
            asm volatile("cp.async.wait_group 1;");
        } else {
            asm volatile("cp.async.wait_group 0;");
        }
        __syncthreads();

        const __nv_bfloat16* sb = sm + (ch & 1) * 4 * TILE_ELEMS;
        const uint32_t bAh = smem_u32(sb);
        const uint32_t bAl = bAh + TILE_ELEMS * 2;
        const uint32_t bBh = bAl + TILE_ELEMS * 2;
        const uint32_t bBl = bBh + TILE_ELEMS * 2;

        uint32_t bh[4][2], bl[4][2];
#pragma unroll
        for (int ntp = 0; ntp < 2; ntp++) {
            uint32_t off = (uint32_t)((wn + ntp * 16) * SPAD + b_off) * 2;
            LDM_X4(bh[2 * ntp][0], bh[2 * ntp][1], bh[2 * ntp + 1][0], bh[2 * ntp + 1][1], bBh + off);
            LDM_X4(bl[2 * ntp][0], bl[2 * ntp][1], bl[2 * ntp + 1][0], bl[2 * ntp + 1][1], bBl + off);
        }
#pragma unroll
        for (int mt = 0; mt < 4; mt++) {
            uint32_t off = (uint32_t)((wm + mt * 16) * SPAD + a_off) * 2;
            uint32_t ah[4], al[4];
            LDM_X4(ah[0], ah[1], ah[2], ah[3], bAh + off);
            LDM_X4(al[0], al[1], al[2], al[3], bAl + off);
#pragma unroll
            for (int nt = 0; nt < 4; nt++) {
                mma_bf16(acc[mt][nt], ah, bh[nt]);
                mma_bf16(acc[mt][nt], ah, bl[nt]);
                mma_bf16(acc[mt][nt], al, bh[nt]);
            }
        }
        __syncthreads();
    }
#undef ISSUE

    // epilogue: direct register stores
#pragma unroll
    for (int mt = 0; mt < 4; mt++) {
#pragma unroll
        for (int nt = 0; nt < 4; nt++) {
            int gm = row0 + wm + mt * 16 + g4;
            int gc = col0 + wn + nt * 8 + t4 * 2;
            if (gm < M)
                *(float2*)&C[(size_t)gm * Nn + gc] = make_float2(acc[mt][nt][0], acc[mt][nt][1]);
            if (gm + 8 < M)
                *(float2*)&C[(size_t)(gm + 8) * Nn + gc] = make_float2(acc[mt][nt][2], acc[mt][nt][3]);
        }
    }
}

// ---------------- alpha: per (node, head) warp dot products ----------------
template <int H>
__global__ void alpha_kernel(const float* __restrict__ hlin,
                             const float* __restrict__ a_src,
                             const float* __restrict__ a_dst,
                             float* __restrict__ asrc,
                             float* __restrict__ adst) {
    int gw = (blockIdx.x * blockDim.x + threadIdx.x) >> 5;
    int lane = threadIdx.x & 31;
    if (gw >= NN * H) return;
    int n = gw / H, h = gw - n * H;
    const float* hp = hlin + ((size_t)n * H + h) * HID;
    const float* as = a_src + h * HID;
    const float* ad = a_dst + h * HID;
    float ss = 0.f, sd = 0.f;
#pragma unroll
    for (int i = 0; i < HID / 32; i++) {
        float v = hp[lane + i * 32];
        ss = fmaf(v, as[lane + i * 32], ss);
        sd = fmaf(v, ad[lane + i * 32], sd);
    }
#pragma unroll
    for (int o = 16; o; o >>= 1) {
        ss += __shfl_xor_sync(0xffffffffu, ss, o);
        sd += __shfl_xor_sync(0xffffffffu, sd, o);
    }
    if (lane == 0) { asrc[gw] = ss; adst[gw] = sd; }
}

// ---------------- edge passes (templated on H) ----------------
template <int H>
__global__ void edgeA_kernel(const int* __restrict__ ei,
                             const float* __restrict__ asrc,
                             const float* __restrict__ adst,
                             float* __restrict__ e_out,
                             float* __restrict__ m) {
    int idx = blockIdx.x * blockDim.x + threadIdx.x;
    if (idx >= ETOT * H) return;
    int e = idx / H, h = idx - e * H;
    int s, d;
    if (e < EE) { s = clampN(ei[e]); d = clampN(ei[EE + e]); } else { s = d = e - EE; }
    float v = asrc[(size_t)s * H + h] + adst[(size_t)d * H + h];
    v = (v > 0.f) ? v : 0.2f * v;
    e_out[idx] = v;
    atomicMaxFloat(&m[(size_t)d * H + h], v);
}

template <int H>
__global__ void edgeB_kernel(const int* __restrict__ ei,
                             float* __restrict__ e_out,
                             const float* __restrict__ m,
                             float* __restrict__ ssum) {
    int idx = blockIdx.x * blockDim.x + threadIdx.x;
    if (idx >= ETOT * H) return;
    int e = idx / H, h = idx - e * H;
    int d;
    if (e < EE) d = clampN(ei[EE + e]); else d = e - EE;
    float ex = expf(e_out[idx] - m[(size_t)d * H + h]);
    e_out[idx] = ex;
    atomicAdd(&ssum[(size_t)d * H + h], ex);
}

template <int H>
__global__ void edgeC_kernel(const int* __restrict__ ei,
                             const float* __restrict__ e_exp,
                             const float* __restrict__ ssum,
                             const float* __restrict__ hlin,
                             float* __restrict__ agg) {
    long long gw = ((long long)blockIdx.x * blockDim.x + threadIdx.x) >> 5;
    int lane = threadIdx.x & 31;
    if (gw >= (long long)ETOT * H) return;
    int e = (int)(gw / H), h = (int)(gw - (long long)e * H);
    int s, d;
    if (e < EE) { s = clampN(ei[e]); d = clampN(ei[EE + e]); } else { s = d = e - EE; }
    float alpha = e_exp[gw] / (ssum[(size_t)d * H + h] + 1e-16f);
    const float4* hp = (const float4*)(hlin + ((size_t)s * H + h) * HID);
    float* op = agg + ((size_t)d * H + h) * HID + lane * 4;
    float4 v = hp[lane];
    asm volatile("red.global.add.v4.f32 [%0], {%1, %2, %3, %4};"
                 :: "l"(op), "f"(v.x * alpha), "f"(v.y * alpha),
                    "f"(v.z * alpha), "f"(v.w * alpha)
                 : "memory");
}

// ---------------- finalize: bias + ELU + bf16 hi/lo split (layers 1,2) ------
__global__ void finalize_split_kernel(const float* __restrict__ agg,
                                      const float* __restrict__ bias,
                                      __nv_bfloat16* __restrict__ hi,
                                      __nv_bfloat16* __restrict__ lo, int F) {
    int idx = blockIdx.x * blockDim.x + threadIdx.x;
    if (idx >= NN * F) return;
    int f = idx % F;
    float v = agg[idx] + bias[f];
    v = (v > 0.f) ? v : expm1f(v);
    __nv_bfloat16 h = __float2bfloat16(v);
    hi[idx] = h;
    lo[idx] = __float2bfloat16(v - __bfloat162float(h));
}

// ---------------- finalize: bias only, fp32 out (layer 3) -------------------
__global__ void finalize_plain_kernel(const float* __restrict__ agg,
                                      const float* __restrict__ bias,
                                      float* __restrict__ out, int F) {
    int idx = blockIdx.x * blockDim.x + threadIdx.x;
    if (idx >= NN * F) return;
    int f = idx % F;
    out[idx] = agg[idx] + bias[f];
}

// ---------------- host orchestration ----------------
struct Buffers {
    float *hlin, *agg, *asrc, *adst, *m, *s, *e_buf;
    __nv_bfloat16 *ah, *al, *wth, *wtl;
};

template <int H>
static void run_layer(int K, const float* W, const float* a_src, const float* a_dst,
                      const float* bias, const Buffers& B, const int* ei,
                      float* out_fp32 /* layer3 only */) {
    const int F = H * HID;
    // init (independent of GEMM)
    {
        int nh = NN * H;
        init_ms_kernel<<<(nh + 255) / 256, 256>>>(B.m, B.s, nh);
        int nf = NN * F;
        fill_kernel<<<(nf + 255) / 256, 256>>>(B.agg, 0.f, nf);
        int nw = K * F;
        splitT_kernel<<<(nw + 255) / 256, 256>>>(W, B.wth, B.wtl, K, F);
    }
    // GEMM
    {
        dim3 grid(F / 128, (NN + 127) / 128);
        hgemm_kernel<<<grid, 256>>>(B.ah, B.al, B.wth, B.wtl, B.hlin, NN, K, F);
    }
    // alpha
    {
        int warps = NN * H;
        alpha_kernel<H><<<(warps * 32 + 255) / 256, 256>>>(B.hlin, a_src, a_dst, B.asrc, B.adst);
    }
    // edge passes
    {
        int nt = ETOT * H;
        edgeA_kernel<H><<<(nt + 255) / 256, 256>>>(ei, B.asrc, B.adst, B.e_buf, B.m);
        edgeB_kernel<H><<<(nt + 255) / 256, 256>>>(ei, B.e_buf, B.m, B.s);
        long long warps = (long long)ETOT * H;
        long long blocks = (warps * 32 + 255) / 256;
        edgeC_kernel<H><<<(unsigned)blocks, 256>>>(ei, B.e_buf, B.s, B.hlin, B.agg);
    }
    // finalize
    {
        int nf = NN * F;
        if (out_fp32)
            finalize_plain_kernel<<<(nf + 255) / 256, 256>>>(B.agg, bias, out_fp32, F);
        else
            finalize_split_kernel<<<(nf + 255) / 256, 256>>>(B.agg, bias, B.ah, B.al, F);
    }
}

extern "C" void kernel_launch(void* const* d_in, const int* in_sizes, int n_in,
                              void* d_out, int out_size) {
    const float* x       = (const float*)d_in[0];
    const int*   ei      = (const int*)d_in[1];     // int64 downcast to int32 by harness
    const float* W1      = (const float*)d_in[2];
    const float* a1_src  = (const float*)d_in[3];
    const float* a1_dst  = (const float*)d_in[4];
    const float* b1      = (const float*)d_in[5];
    const float* W2      = (const float*)d_in[6];
    const float* a2_src  = (const float*)d_in[7];
    const float* a2_dst  = (const float*)d_in[8];
    const float* b2      = (const float*)d_in[9];
    const float* W3      = (const float*)d_in[10];
    const float* a3_src  = (const float*)d_in[11];
    const float* a3_dst  = (const float*)d_in[12];
    const float* b3      = (const float*)d_in[13];

    Buffers B;
    cudaGetSymbolAddress((void**)&B.hlin,  g_hlin);
    cudaGetSymbolAddress((void**)&B.agg,   g_agg);
    cudaGetSymbolAddress((void**)&B.asrc,  g_asrc);
    cudaGetSymbolAddress((void**)&B.adst,  g_adst);
    cudaGetSymbolAddress((void**)&B.m,     g_m);
    cudaGetSymbolAddress((void**)&B.s,     g_s);
    cudaGetSymbolAddress((void**)&B.e_buf, g_e);
    cudaGetSymbolAddress((void**)&B.ah,    g_ah);
    cudaGetSymbolAddress((void**)&B.al,    g_al);
    cudaGetSymbolAddress((void**)&B.wth,   g_wth);
    cudaGetSymbolAddress((void**)&B.wtl,   g_wtl);

    // split x into bf16 hi/lo once (layer 1 GEMM input)
    {
        int na = NN * INC;
        split_kernel<<<(na + 255) / 256, 256>>>(x, B.ah, B.al, na);
    }
    run_layer<HEADS>(INC,  W1, a1_src, a1_dst, b1, B, ei, nullptr);
    run_layer<HEADS>(FMAX, W2, a2_src, a2_dst, b2, B, ei, nullptr);
    run_layer<1>    (FMAX, W3, a3_src, a3_dst, b3, B, ei, (float*)d_out);
}

// round 7
// speedup vs baseline: 5.3070x; 1.7460x over previous
#include <cuda_runtime.h>
#include <cuda_bf16.h>
#include <math.h>
#include <stdint.h>

// Problem constants
#define NN     20000
#define EE     400000
#define ETOT   420000
#define INC    768
#define HID    128
#define HEADS  4
#define FMAX   512

// ---------------- device scratch ----------------
__device__ float g_hlin[(size_t)NN * FMAX];
__device__ float g_asrc[(size_t)NN * HEADS];
__device__ float g_adst[(size_t)NN * HEADS];
__device__ __nv_bfloat16 g_ah [(size_t)NN * INC];
__device__ __nv_bfloat16 g_al [(size_t)NN * INC];
__device__ __nv_bfloat16 g_wth[(size_t)FMAX * INC];
__device__ __nv_bfloat16 g_wtl[(size_t)FMAX * INC];
// CSR (built once per launch)
__device__ int g_deg[NN];
__device__ int g_cur[NN];
__device__ int g_rowptr[NN + 1];
__device__ int g_eperm[ETOT];

// ---------------- misc helpers ----------------
__device__ __forceinline__ int clampN(int v) { return v < 0 ? 0 : (v >= NN ? NN - 1 : v); }
__device__ __forceinline__ uint32_t smem_u32(const void* p) {
    uint32_t a;
    asm("{ .reg .u64 t; cvta.to.shared.u64 t, %1; cvt.u32.u64 %0, t; }" : "=r"(a) : "l"(p));
    return a;
}

__global__ void zero_int2_kernel(int* __restrict__ a, int* __restrict__ b, int n) {
    int i = blockIdx.x * blockDim.x + threadIdx.x;
    if (i < n) { a[i] = 0; b[i] = 0; }
}

// ---------------- CSR build ----------------
__global__ void count_kernel(const int* __restrict__ ei, int* __restrict__ deg) {
    int e = blockIdx.x * blockDim.x + threadIdx.x;
    if (e >= ETOT) return;
    int d = (e < EE) ? clampN(ei[EE + e]) : e - EE;
    atomicAdd(&deg[d], 1);
}

#define SCAN_T 1024
#define SCAN_CH 20
__global__ void scan_kernel(const int* __restrict__ deg, int* __restrict__ rowptr) {
    __shared__ int sums[SCAN_T];
    int t = threadIdx.x;
    int base = t * SCAN_CH;
    int local = 0;
#pragma unroll
    for (int i = 0; i < SCAN_CH; i++) {
        int idx = base + i;
        if (idx < NN) local += deg[idx];
    }
    sums[t] = local;
    __syncthreads();
    for (int off = 1; off < SCAN_T; off <<= 1) {
        int v = (t >= off) ? sums[t - off] : 0;
        __syncthreads();
        sums[t] += v;
        __syncthreads();
    }
    int run = sums[t] - local;   // exclusive prefix
#pragma unroll
    for (int i = 0; i < SCAN_CH; i++) {
        int idx = base + i;
        if (idx < NN) { rowptr[idx] = run; run += deg[idx]; }
    }
    if (t == SCAN_T - 1) rowptr[NN] = sums[SCAN_T - 1];
}

__global__ void scatter_kernel(const int* __restrict__ ei,
                               const int* __restrict__ rowptr,
                               int* __restrict__ cur, int* __restrict__ eperm) {
    int e = blockIdx.x * blockDim.x + threadIdx.x;
    if (e >= ETOT) return;
    int d = (e < EE) ? clampN(ei[EE + e]) : e - EE;
    int pos = rowptr[d] + atomicAdd(&cur[d], 1);
    eperm[pos] = e;
}

// ---------------- fp32 -> bf16 hi/lo split (layer-1 input x only) ----------
__global__ void split_kernel(const float* __restrict__ x,
                             __nv_bfloat16* __restrict__ hi,
                             __nv_bfloat16* __restrict__ lo, int n) {
    int i = blockIdx.x * blockDim.x + threadIdx.x;
    if (i >= n) return;
    float v = x[i];
    __nv_bfloat16 h = __float2bfloat16(v);
    hi[i] = h;
    lo[i] = __float2bfloat16(v - __bfloat162float(h));
}

// W [K,N] fp32 -> Wt hi/lo [N,K] bf16 (transposed)
__global__ void splitT_kernel(const float* __restrict__ W,
                              __nv_bfloat16* __restrict__ hi,
                              __nv_bfloat16* __restrict__ lo, int K, int Nn) {
    int i = blockIdx.x * blockDim.x + threadIdx.x;
    if (i >= K * Nn) return;
    int k = i / Nn, n = i - k * Nn;
    float v = W[i];
    __nv_bfloat16 h = __float2bfloat16(v);
    size_t o = (size_t)n * K + k;
    hi[o] = h;
    lo[o] = __float2bfloat16(v - __bfloat162float(h));
}

// ---------------- HMMA bf16 GEMM with cp.async + ldmatrix ----------------
#define SPAD 24
#define TILE_ELEMS (128 * SPAD)

__device__ __forceinline__ void mma_bf16(float* c, const uint32_t* a, const uint32_t* b) {
    asm volatile("mma.sync.aligned.m16n8k16.row.col.f32.bf16.bf16.f32 "
                 "{%0,%1,%2,%3}, {%4,%5,%6,%7}, {%8,%9}, {%0,%1,%2,%3};"
                 : "+f"(c[0]), "+f"(c[1]), "+f"(c[2]), "+f"(c[3])
                 : "r"(a[0]), "r"(a[1]), "r"(a[2]), "r"(a[3]),
                   "r"(b[0]), "r"(b[1]));
}
#define LDM_X4(r0, r1, r2, r3, a) \
    asm volatile("ldmatrix.sync.aligned.m8n8.x4.shared.b16 {%0,%1,%2,%3}, [%4];" \
                 : "=r"(r0), "=r"(r1), "=r"(r2), "=r"(r3) : "r"(a))
#define CP_ASYNC16(dst, src) \
    asm volatile("cp.async.ca.shared.global [%0], [%1], 16;" :: "r"(dst), "l"(src))

__global__ void __launch_bounds__(256)
hgemm_kernel(const __nv_bfloat16* __restrict__ Ah,
             const __nv_bfloat16* __restrict__ Al,
             const __nv_bfloat16* __restrict__ Bh,
             const __nv_bfloat16* __restrict__ Bl,
             float* __restrict__ C, int M, int K, int Nn) {
    __shared__ __nv_bfloat16 sm[2 * 4 * TILE_ELEMS];

    const int tid  = threadIdx.x;
    const int lane = tid & 31;
    const int wid  = tid >> 5;
    const int wm   = (wid >> 2) * 64;
    const int wn   = (wid & 3) * 32;
    const int row0 = blockIdx.y * 128;
    const int col0 = blockIdx.x * 128;
    const int g4   = lane >> 2;
    const int t4   = lane & 3;

    const int a_off = (lane & 15) * SPAD + (lane >> 4) * 8;
    const int b_off = ((lane & 7) + ((lane & 16) ? 8 : 0)) * SPAD + ((lane & 8) ? 8 : 0);

    const int lr = tid >> 1;
    const int lc = (tid & 1) * 8;

    float acc[4][4][4];
#pragma unroll
    for (int a = 0; a < 4; a++)
#pragma unroll
        for (int b = 0; b < 4; b++)
#pragma unroll
            for (int c = 0; c < 4; c++) acc[a][b][c] = 0.f;

    const int nCh = K >> 4;
    const int gra = min(row0 + lr, M - 1);
    const int grb = col0 + lr;

#define ISSUE(ch) do {                                                          \
    __nv_bfloat16* sb_ = sm + ((ch) & 1) * 4 * TILE_ELEMS;                      \
    int kc0_ = (ch) << 4;                                                       \
    uint32_t d0 = smem_u32(sb_ + 0 * TILE_ELEMS + lr * SPAD + lc);              \
    uint32_t d1 = smem_u32(sb_ + 1 * TILE_ELEMS + lr * SPAD + lc);              \
    uint32_t d2 = smem_u32(sb_ + 2 * TILE_ELEMS + lr * SPAD + lc);              \
    uint32_t d3 = smem_u32(sb_ + 3 * TILE_ELEMS + lr * SPAD + lc);              \
    CP_ASYNC16(d0, Ah + (size_t)gra * K + kc0_ + lc);                           \
    CP_ASYNC16(d1, Al + (size_t)gra * K + kc0_ + lc);                           \
    CP_ASYNC16(d2, Bh + (size_t)grb * K + kc0_ + lc);                           \
    CP_ASYNC16(d3, Bl + (size_t)grb * K + kc0_ + lc);                           \
    asm volatile("cp.async.commit_group;");                                     \
} while (0)

    ISSUE(0);
    for (int ch = 0; ch < nCh; ch++) {
        if (ch + 1 < nCh) {
            ISSUE(ch + 1);
            asm volatile("cp.async.wait_group 1;");
        } else {
            asm volatile("cp.async.wait_group 0;");
        }
        __syncthreads();

        const __nv_bfloat16* sb = sm + (ch & 1) * 4 * TILE_ELEMS;
        const uint32_t bAh = smem_u32(sb);
        const uint32_t bAl = bAh + TILE_ELEMS * 2;
        const uint32_t bBh = bAl + TILE_ELEMS * 2;
        const uint32_t bBl = bBh + TILE_ELEMS * 2;

        uint32_t bh[4][2], bl[4][2];
#pragma unroll
        for (int ntp = 0; ntp < 2; ntp++) {
            uint32_t off = (uint32_t)((wn + ntp * 16) * SPAD + b_off) * 2;
            LDM_X4(bh[2 * ntp][0], bh[2 * ntp][1], bh[2 * ntp + 1][0], bh[2 * ntp + 1][1], bBh + off);
            LDM_X4(bl[2 * ntp][0], bl[2 * ntp][1], bl[2 * ntp + 1][0], bl[2 * ntp + 1][1], bBl + off);
        }
#pragma unroll
        for (int mt = 0; mt < 4; mt++) {
            uint32_t off = (uint32_t)((wm + mt * 16) * SPAD + a_off) * 2;
            uint32_t ah[4], al[4];
            LDM_X4(ah[0], ah[1], ah[2], ah[3], bAh + off);
            LDM_X4(al[0], al[1], al[2], al[3], bAl + off);
#pragma unroll
            for (int nt = 0; nt < 4; nt++) {
                mma_bf16(acc[mt][nt], ah, bh[nt]);
                mma_bf16(acc[mt][nt], ah, bl[nt]);
                mma_bf16(acc[mt][nt], al, bh[nt]);
            }
        }
        __syncthreads();
    }
#undef ISSUE

#pragma unroll
    for (int mt = 0; mt < 4; mt++) {
#pragma unroll
        for (int nt = 0; nt < 4; nt++) {
            int gm = row0 + wm + mt * 16 + g4;
            int gc = col0 + wn + nt * 8 + t4 * 2;
            if (gm < M)
                *(float2*)&C[(size_t)gm * Nn + gc] = make_float2(acc[mt][nt][0], acc[mt][nt][1]);
            if (gm + 8 < M)
                *(float2*)&C[(size_t)(gm + 8) * Nn + gc] = make_float2(acc[mt][nt][2], acc[mt][nt][3]);
        }
    }
}

// ---------------- alpha: per (node, head) warp dot products ----------------
template <int H>
__global__ void alpha_kernel(const float* __restrict__ hlin,
                             const float* __restrict__ a_src,
                             const float* __restrict__ a_dst,
                             float* __restrict__ asrc,
                             float* __restrict__ adst) {
    int gw = (blockIdx.x * blockDim.x + threadIdx.x) >> 5;
    int lane = threadIdx.x & 31;
    if (gw >= NN * H) return;
    int n = gw / H, h = gw - n * H;
    const float* hp = hlin + ((size_t)n * H + h) * HID;
    const float* as = a_src + h * HID;
    const float* ad = a_dst + h * HID;
    float ss = 0.f, sd = 0.f;
#pragma unroll
    for (int i = 0; i < HID / 32; i++) {
        float v = hp[lane + i * 32];
        ss = fmaf(v, as[lane + i * 32], ss);
        sd = fmaf(v, ad[lane + i * 32], sd);
    }
#pragma unroll
    for (int o = 16; o; o >>= 1) {
        ss += __shfl_xor_sync(0xffffffffu, ss, o);
        sd += __shfl_xor_sync(0xffffffffu, sd, o);
    }
    if (lane == 0) { asrc[gw] = ss; adst[gw] = sd; }
}

// ---------------- fused aggregate: softmax + weighted gather + finalize ----
// warp per (dst, head). No atomics. MODE 0: +bias,ELU,bf16 split; MODE 1: +bias fp32.
template <int H, int MODE>
__global__ void aggregate_kernel(const int* __restrict__ ei,
                                 const int* __restrict__ rowptr,
                                 const int* __restrict__ eperm,
                                 const float* __restrict__ asrc,
                                 const float* __restrict__ adst,
                                 const float* __restrict__ hlin,
                                 const float* __restrict__ bias,
                                 __nv_bfloat16* __restrict__ hi,
                                 __nv_bfloat16* __restrict__ lo,
                                 float* __restrict__ out) {
    int gw = (blockIdx.x * blockDim.x + threadIdx.x) >> 5;
    int lane = threadIdx.x & 31;
    if (gw >= NN * H) return;
    int n = gw / H, h = gw - n * H;
    float adst_nh = adst[gw];
    int beg = rowptr[n], end = rowptr[n + 1];

    float4 acc = make_float4(0.f, 0.f, 0.f, 0.f);
    float ssum = 0.f;

    for (int base = beg; base < end; base += 32) {
        int j = base + lane;
        float vj = 0.f;
        int sj = 0;
        if (j < end) {
            int e = eperm[j];
            sj = (e < EE) ? clampN(ei[e]) : e - EE;
            float v = asrc[(size_t)sj * H + h] + adst_nh;
            v = (v > 0.f) ? v : 0.2f * v;
            vj = __expf(v);
        }
        int cnt = min(32, end - base);
        for (int t = 0; t < cnt; t++) {
            float v = __shfl_sync(0xffffffffu, vj, t);
            int s   = __shfl_sync(0xffffffffu, sj, t);
            const float4* hp = (const float4*)(hlin + ((size_t)s * H + h) * HID);
            float4 hv = hp[lane];
            acc.x = fmaf(v, hv.x, acc.x);
            acc.y = fmaf(v, hv.y, acc.y);
            acc.z = fmaf(v, hv.z, acc.z);
            acc.w = fmaf(v, hv.w, acc.w);
            ssum += v;
        }
    }
    float inv = 1.f / (ssum + 1e-16f);
    int f = h * HID + lane * 4;
    float4 bv = *(const float4*)(bias + f);
    float4 o;
    o.x = acc.x * inv + bv.x;
    o.y = acc.y * inv + bv.y;
    o.z = acc.z * inv + bv.z;
    o.w = acc.w * inv + bv.w;
    if (MODE == 0) {
        o.x = (o.x > 0.f) ? o.x : expm1f(o.x);
        o.y = (o.y > 0.f) ? o.y : expm1f(o.y);
        o.z = (o.z > 0.f) ? o.z : expm1f(o.z);
        o.w = (o.w > 0.f) ? o.w : expm1f(o.w);
        size_t off = (size_t)gw * HID + lane * 4;
        __nv_bfloat16 hx = __float2bfloat16(o.x);
        __nv_bfloat16 hy = __float2bfloat16(o.y);
        __nv_bfloat16 hz = __float2bfloat16(o.z);
        __nv_bfloat16 hw = __float2bfloat16(o.w);
        hi[off + 0] = hx;  lo[off + 0] = __float2bfloat16(o.x - __bfloat162float(hx));
        hi[off + 1] = hy;  lo[off + 1] = __float2bfloat16(o.y - __bfloat162float(hy));
        hi[off + 2] = hz;  lo[off + 2] = __float2bfloat16(o.z - __bfloat162float(hz));
        hi[off + 3] = hw;  lo[off + 3] = __float2bfloat16(o.w - __bfloat162float(hw));
    } else {
        *(float4*)&out[(size_t)n * HID + lane * 4] = o;
    }
}

// ---------------- host orchestration ----------------
struct Buffers {
    float *hlin, *asrc, *adst;
    __nv_bfloat16 *ah, *al, *wth, *wtl;
    int *deg, *cur, *rowptr, *eperm;
};

template <int H, int MODE>
static void run_layer(int K, const float* W, const float* a_src, const float* a_dst,
                      const float* bias, const Buffers& B, const int* ei, float* out_fp32) {
    const int F = H * HID;
    {
        int nw = K * F;
        splitT_kernel<<<(nw + 255) / 256, 256>>>(W, B.wth, B.wtl, K, F);
    }
    {
        dim3 grid(F / 128, (NN + 127) / 128);
        hgemm_kernel<<<grid, 256>>>(B.ah, B.al, B.wth, B.wtl, B.hlin, NN, K, F);
    }
    {
        int warps = NN * H;
        alpha_kernel<H><<<(warps * 32 + 255) / 256, 256>>>(B.hlin, a_src, a_dst, B.asrc, B.adst);
    }
    {
        int warps = NN * H;
        aggregate_kernel<H, MODE><<<(warps * 32 + 255) / 256, 256>>>(
            ei, B.rowptr, B.eperm, B.asrc, B.adst, B.hlin, bias, B.ah, B.al, out_fp32);
    }
}

extern "C" void kernel_launch(void* const* d_in, const int* in_sizes, int n_in,
                              void* d_out, int out_size) {
    const float* x       = (const float*)d_in[0];
    const int*   ei      = (const int*)d_in[1];
    const float* W1      = (const float*)d_in[2];
    const float* a1_src  = (const float*)d_in[3];
    const float* a1_dst  = (const float*)d_in[4];
    const float* b1      = (const float*)d_in[5];
    const float* W2      = (const float*)d_in[6];
    const float* a2_src  = (const float*)d_in[7];
    const float* a2_dst  = (const float*)d_in[8];
    const float* b2      = (const float*)d_in[9];
    const float* W3      = (const float*)d_in[10];
    const float* a3_src  = (const float*)d_in[11];
    const float* a3_dst  = (const float*)d_in[12];
    const float* b3      = (const float*)d_in[13];

    Buffers B;
    cudaGetSymbolAddress((void**)&B.hlin,   g_hlin);
    cudaGetSymbolAddress((void**)&B.asrc,   g_asrc);
    cudaGetSymbolAddress((void**)&B.adst,   g_adst);
    cudaGetSymbolAddress((void**)&B.ah,     g_ah);
    cudaGetSymbolAddress((void**)&B.al,     g_al);
    cudaGetSymbolAddress((void**)&B.wth,    g_wth);
    cudaGetSymbolAddress((void**)&B.wtl,    g_wtl);
    cudaGetSymbolAddress((void**)&B.deg,    g_deg);
    cudaGetSymbolAddress((void**)&B.cur,    g_cur);
    cudaGetSymbolAddress((void**)&B.rowptr, g_rowptr);
    cudaGetSymbolAddress((void**)&B.eperm,  g_eperm);

    // CSR build (once; reused by all 3 layers)
    zero_int2_kernel<<<(NN + 255) / 256, 256>>>(B.deg, B.cur, NN);
    count_kernel<<<(ETOT + 255) / 256, 256>>>(ei, B.deg);
    scan_kernel<<<1, SCAN_T>>>(B.deg, B.rowptr);
    scatter_kernel<<<(ETOT + 255) / 256, 256>>>(ei, B.rowptr, B.cur, B.eperm);

    // split x into bf16 hi/lo (layer-1 GEMM input)
    {
        int na = NN * INC;
        split_kernel<<<(na + 255) / 256, 256>>>(x, B.ah, B.al, na);
    }
    run_layer<HEADS, 0>(INC,  W1, a1_src, a1_dst, b1, B, ei, nullptr);
    run_layer<HEADS, 0>(FMAX, W2, a2_src, a2_dst, b2, B, ei, nullptr);
    run_layer<1, 1>    (FMAX, W3, a3_src, a3_dst, b3, B, ei, (float*)d_out);
}